// round 16
// baseline (speedup 1.0000x reference)
#include <cuda_runtime.h>

// B, N, D, L = 32, 1000, 256, 3
#define BB 32
#define NN 1000
#define DD 256
#define LL 3
#define CHUNKS 36
#define ROWS_PER_CHUNK 28          // 36 * 28 = 1008 >= 1000 (guarded)
#define TOTAL4 (BB * NN * DD / 4)  // 2,048,000 float4 per output half
#define B4 (NN * DD / 4)           // 64,000 float4 per batch
#define NOUT 400                   // out blocks: 400 * 1024thr * 5 f4 = TOTAL4

// Scratch (no device allocation allowed -> __device__ globals)
__device__ float g_partial[BB * CHUNKS * DD];
__device__ float g_v[BB * DD];
__device__ int   g_done;           // zeroed by K1 each call -> replay-safe

// ---------------------------------------------------------------------------
// K1: partial sums over the node axis (proven single-wave shape) + flag reset.
// ---------------------------------------------------------------------------
__global__ __launch_bounds__(256)
void k_partial_mean(const float* __restrict__ nf) {
    if (blockIdx.x == 0 && blockIdx.y == 0 && threadIdx.x == 0 && threadIdx.y == 0)
        g_done = 0;                // ordered before K2 by the kernel boundary

    const int b = blockIdx.x;
    const int c = blockIdx.y;
    const int x = threadIdx.x;   // 0..63
    const int y = threadIdx.y;   // 0..3

    const float4* __restrict__ nf4 = reinterpret_cast<const float4*>(nf);
    const float4 z4 = make_float4(0.f, 0.f, 0.f, 0.f);
    const int row0 = c * ROWS_PER_CHUNK;
    const int base = (b * NN + row0) * 64;

    float4 a[7];
#pragma unroll
    for (int i = 0; i < 7; i++) {
        const int r = y + 4 * i;
        a[i] = (row0 + r < NN) ? nf4[base + r * 64 + x] : z4;
    }

    float4 s0 = z4, s1 = z4;
#pragma unroll
    for (int i = 0; i < 6; i += 2) {
        s0.x += a[i].x;   s0.y += a[i].y;   s0.z += a[i].z;   s0.w += a[i].w;
        s1.x += a[i+1].x; s1.y += a[i+1].y; s1.z += a[i+1].z; s1.w += a[i+1].w;
    }
    float4 s;
    s.x = s0.x + s1.x + a[6].x;
    s.y = s0.y + s1.y + a[6].y;
    s.z = s0.z + s1.z + a[6].z;
    s.w = s0.w + s1.w + a[6].w;

    __shared__ float4 sm[4][64];
    sm[y][x] = s;
    __syncthreads();
    if (y == 0) {
        float4 t = sm[0][x];
        const float4 t1 = sm[1][x], t2 = sm[2][x], t3 = sm[3][x];
        t.x += t1.x + t2.x + t3.x;
        t.y += t1.y + t2.y + t3.y;
        t.z += t1.z + t2.z + t3.z;
        t.w += t1.w + t2.w + t3.w;
        reinterpret_cast<float4*>(g_partial)[(b * CHUNKS + c) * 64 + x] = t;
    }
}

// ---------------------------------------------------------------------------
// K2'': heterogeneous blocks, flag-synchronized.
//   bid < 32 : GEMV for batch bid (champion 1024-thr / K-split-4 shape),
//              then threadfence + atomicAdd(g_done). NEVER waits -> no deadlock.
//   bid >= 32: out block. Prologue = 5 nf loads + 5 copy-half stores
//              (independent of v, hides the GEMV). Then spin g_done==32,
//              then add-half stores.
// ---------------------------------------------------------------------------
__global__ __launch_bounds__(1024)
void k_gemv_out(const float* __restrict__ nf,
                const float* __restrict__ Ws,
                const float* __restrict__ bs,
                float* __restrict__ out) {
    const int bid = blockIdx.x;
    const int t = threadIdx.x;

    if (bid < BB) {
        // ---------------- GEMV block for batch b = bid ----------------
        const int b = bid;
        const int o = t & (DD - 1);
        const int g = t >> 8;       // 0..3

        __shared__ float sv[DD];
        __shared__ float part[4][DD];

        float s = 0.f;
#pragma unroll
        for (int c = g; c < CHUNKS; c += 4)
            s += g_partial[(b * CHUNKS + c) * DD + o];
        part[g][o] = s;
        __syncthreads();
        if (g == 0)
            sv[o] = (part[0][o] + part[1][o] + part[2][o] + part[3][o]) * (1.0f / (float)NN);
        __syncthreads();

#pragma unroll
        for (int l = 0; l < LL; l++) {
            const float* __restrict__ W = Ws + l * DD * DD;
            float acc = 0.f;
            const int k0 = g * 64;
#pragma unroll 8
            for (int k = k0; k < k0 + 64; k++)
                acc = fmaf(sv[k], W[k * DD + o], acc);   // coalesced, L2-resident
            part[g][o] = acc;
            __syncthreads();
            if (g == 0) {
                float r = part[0][o] + part[1][o] + part[2][o] + part[3][o] + bs[l * DD + o];
                sv[o] = (l < LL - 1) ? fmaxf(r, 0.f) : r;
            }
            __syncthreads();
        }
        if (g == 0) g_v[b * DD + o] = sv[o];

        // publish
        __syncthreads();
        __threadfence();
        if (t == 0) atomicAdd(&g_done, 1);
    } else {
        // ---------------- out block ----------------
        const int k = bid - BB;                 // 0..399
        const int base = k * 5120;              // 1024 thr * 5 f4, contiguous

        const float4* __restrict__ nf4 = reinterpret_cast<const float4*>(nf);
        float4* oa = reinterpret_cast<float4*>(out);            // add half
        float4* oc = reinterpret_cast<float4*>(out) + TOTAL4;   // copy half

        const int j0 = base + t;
        const int j1 = j0 + 1024, j2 = j0 + 2048, j3 = j0 + 3072, j4 = j0 + 4096;

        // prologue: loads + copy half (independent of v -> overlaps GEMV)
        const float4 a0 = nf4[j0];
        const float4 a1 = nf4[j1];
        const float4 a2 = nf4[j2];
        const float4 a3 = nf4[j3];
        const float4 a4 = nf4[j4];

        __stcs(oc + j0, a0);
        __stcs(oc + j1, a1);
        __stcs(oc + j2, a2);
        __stcs(oc + j3, a3);
        __stcs(oc + j4, a4);

        // wait for all 32 GEMV blocks (they never wait on us -> safe)
        if (t == 0) {
            while (*(volatile int*)&g_done < BB) { __nanosleep(64); }
        }
        __syncthreads();
        __threadfence();   // acquire g_v

#define DO_ONE(jj, aa)                                                        \
        {                                                                     \
            const int bb = (jj) / B4;                                         \
            const float4 v = *reinterpret_cast<const float4*>(                \
                g_v + bb * DD + (((jj) & 63) << 2));                          \
            float4 r;                                                         \
            r.x = (aa).x + v.x; r.y = (aa).y + v.y;                           \
            r.z = (aa).z + v.z; r.w = (aa).w + v.w;                           \
            __stcs(oa + (jj), r);                                             \
        }
        DO_ONE(j0, a0)
        DO_ONE(j1, a1)
        DO_ONE(j2, a2)
        DO_ONE(j3, a3)
        DO_ONE(j4, a4)
#undef DO_ONE
    }
}

extern "C" void kernel_launch(void* const* d_in, const int* in_sizes, int n_in,
                              void* d_out, int out_size) {
    // Inputs in metadata order: x (unused), node_feature, Ws, bs
    const float* nf = (const float*)d_in[1];
    const float* Ws = (const float*)d_in[2];
    const float* bs = (const float*)d_in[3];
    float* out = (float*)d_out;

    dim3 g1(BB, CHUNKS);      // 1152 CTAs — single wave
    dim3 b1(64, 4);
    k_partial_mean<<<g1, b1>>>(nf);

    k_gemv_out<<<BB + NOUT, 1024>>>(nf, Ws, bs, out);   // 432 blocks
}